// round 5
// baseline (speedup 1.0000x reference)
#include <cuda_runtime.h>

// CrossNetwork: x_l = x0 * (x_l . W_l) + b_l + x_l, L=6 layers.
// Identity: x_l = alpha_l * x0 + sum_{i<l} b_i, with
//   d_l = x0 . W_l ; C_l = (sum_{i<l} b_i) . W_l
//   s_l = alpha_l * d_l + C_l ; alpha_{l+1} = alpha_l + s_l ; alpha_0 = 1
//   out = alpha_L * x0 + sum_i b_i
// One read of x, one write of out: ~256 MB HBM traffic.
// R1: L1tex-bound (82%) from re-fetching W every row -> W/bsum in registers,
//     8 rows per block, 1 barrier per row (double-buffered partials).
// R2 bug: cross-warp reduction assumed 48 lanes. Fixed with a 2-value
//     load + 8-group butterfly (shfl_xor 1,2,4) + 6 broadcasts.

#define D_DIM 2048
#define L_DIM 6
#define D_VEC (D_DIM / 4)      // 512 float4 per row
#define TPB   256
#define NWARP (TPB / 32)       // 8
#define ROWS_PER_BLK 8
#define PRE_BLKS 8

__device__ float g_Cpart[PRE_BLKS][L_DIM];  // per-block partial C_l
__device__ float g_bsum[D_DIM];             // sum_i b_i

// ---------------------------------------------------------------------------
// Kernel 1: 8 blocks x 256 threads; one column per thread. ~2us.
// ---------------------------------------------------------------------------
__global__ __launch_bounds__(TPB) void precompute_kernel(
    const float* __restrict__ W, const float* __restrict__ b)
{
    const int t = threadIdx.x;
    const int d = blockIdx.x * TPB + t;     // 0..2047, exact cover

    float pc[L_DIM];
    float pre = 0.f;                         // prefix of b_i[d], i < l
#pragma unroll
    for (int l = 0; l < L_DIM; ++l) {
        pc[l] = pre * W[l * D_DIM + d];
        pre += b[l * D_DIM + d];
    }
    g_bsum[d] = pre;

#pragma unroll
    for (int l = 0; l < L_DIM; ++l) {
#pragma unroll
        for (int o = 16; o > 0; o >>= 1)
            pc[l] += __shfl_xor_sync(0xffffffffu, pc[l], o);
    }
    __shared__ float sred[NWARP][L_DIM];
    const int warp = t >> 5, lane = t & 31;
    if (lane == 0) {
#pragma unroll
        for (int l = 0; l < L_DIM; ++l) sred[warp][l] = pc[l];
    }
    __syncthreads();
    if (warp == 0) {
#pragma unroll
        for (int l = 0; l < L_DIM; ++l) {
            float v = (lane < NWARP) ? sred[lane][l] : 0.f;
#pragma unroll
            for (int o = 4; o > 0; o >>= 1)
                v += __shfl_xor_sync(0xffffffffu, v, o);
            if (lane == 0) g_Cpart[blockIdx.x][l] = v;
        }
    }
}

// ---------------------------------------------------------------------------
// Kernel 2: one block per 8 rows. W, bsum, C hoisted to registers.
// ---------------------------------------------------------------------------
__global__ __launch_bounds__(TPB) void cross_kernel(
    const float* __restrict__ x, const float* __restrict__ W,
    float* __restrict__ out)
{
    const int t = threadIdx.x;
    const int warp = t >> 5, lane = t & 31;

    // Row-invariant data -> registers (once per block).
    float4 wa[L_DIM], wb[L_DIM];
#pragma unroll
    for (int l = 0; l < L_DIM; ++l) {
        const float4* w4 = reinterpret_cast<const float4*>(W) + l * D_VEC;
        wa[l] = __ldg(&w4[t]);
        wb[l] = __ldg(&w4[t + TPB]);
    }
    const float4* bs4 = reinterpret_cast<const float4*>(g_bsum);
    const float4 ba = bs4[t];
    const float4 bb = bs4[t + TPB];

    float C[L_DIM];
#pragma unroll
    for (int l = 0; l < L_DIM; ++l) {
        float c = 0.f;
#pragma unroll
        for (int j = 0; j < PRE_BLKS; ++j) c += g_Cpart[j][l];
        C[l] = c;
    }

    __shared__ float sred[2][NWARP][L_DIM + 2];  // double-buffered (+pad)

    const size_t base = (size_t)blockIdx.x * ROWS_PER_BLK * D_VEC;
    const float4* x4base = reinterpret_cast<const float4*>(x) + base;
    float4* o4base = reinterpret_cast<float4*>(out) + base;

#pragma unroll
    for (int r = 0; r < ROWS_PER_BLK; ++r) {
        const float4* x4 = x4base + r * D_VEC;
        const float4 xa = __ldcs(&x4[t]);
        const float4 xb = __ldcs(&x4[t + TPB]);

        // 6 dot partials (W in registers -> no L1 traffic).
        float p[L_DIM];
#pragma unroll
        for (int l = 0; l < L_DIM; ++l) {
            p[l] = xa.x * wa[l].x + xa.y * wa[l].y + xa.z * wa[l].z + xa.w * wa[l].w
                 + xb.x * wb[l].x + xb.y * wb[l].y + xb.z * wb[l].z + xb.w * wb[l].w;
        }
#pragma unroll
        for (int l = 0; l < L_DIM; ++l) {
#pragma unroll
            for (int o = 16; o > 0; o >>= 1)
                p[l] += __shfl_xor_sync(0xffffffffu, p[l], o);
        }
        if (lane == 0) {
#pragma unroll
            for (int l = 0; l < L_DIM; ++l) sred[r & 1][warp][l] = p[l];
        }
        __syncthreads();  // single barrier per row (double buffer makes it safe)

        // Cross-warp reduction, every warp redundantly (no 2nd barrier).
        // v1 covers (wp=lane&7, l=lane>>3) for l=0..3; v2 covers l=4,5.
        const int wp = lane & 7;
        const int lsel = lane >> 3;                   // 0..3
        float v1 = sred[r & 1][wp][lsel];
        float v2 = (lane < 16) ? sred[r & 1][wp][4 + lsel] : 0.f;
#pragma unroll
        for (int o = 1; o < 8; o <<= 1) {
            v1 += __shfl_xor_sync(0xffffffffu, v1, o);
            v2 += __shfl_xor_sync(0xffffffffu, v2, o);
        }
        // group g (lanes 8g..8g+7) of v1 holds d_g; v2 groups 0,1 hold d_4,d_5.
        float d[L_DIM];
        d[0] = __shfl_sync(0xffffffffu, v1, 0);
        d[1] = __shfl_sync(0xffffffffu, v1, 8);
        d[2] = __shfl_sync(0xffffffffu, v1, 16);
        d[3] = __shfl_sync(0xffffffffu, v1, 24);
        d[4] = __shfl_sync(0xffffffffu, v2, 0);
        d[5] = __shfl_sync(0xffffffffu, v2, 8);

        float alpha = 1.f;
#pragma unroll
        for (int l = 0; l < L_DIM; ++l)
            alpha += alpha * d[l] + C[l];

        // out = alpha * x0 + bsum (streaming store, no reuse)
        float4 oa, ob;
        oa.x = alpha * xa.x + ba.x;  oa.y = alpha * xa.y + ba.y;
        oa.z = alpha * xa.z + ba.z;  oa.w = alpha * xa.w + ba.w;
        ob.x = alpha * xb.x + bb.x;  ob.y = alpha * xb.y + bb.y;
        ob.z = alpha * xb.z + bb.z;  ob.w = alpha * xb.w + bb.w;

        float4* o4 = o4base + r * D_VEC;
        __stcs(&o4[t], oa);
        __stcs(&o4[t + TPB], ob);
    }
}

// ---------------------------------------------------------------------------
extern "C" void kernel_launch(void* const* d_in, const int* in_sizes, int n_in,
                              void* d_out, int out_size)
{
    const float* x = (const float*)d_in[0];   // [B, 2048]
    const float* W = (const float*)d_in[1];   // [6, 2048]
    const float* b = (const float*)d_in[2];   // [6, 2048]
    float* out = (float*)d_out;               // [B, 2048]

    const int B = in_sizes[0] / D_DIM;

    precompute_kernel<<<PRE_BLKS, TPB>>>(W, b);
    cross_kernel<<<B / ROWS_PER_BLK, TPB>>>(x, W, out);
}

// round 7
// speedup vs baseline: 1.3433x; 1.3433x over previous
#include <cuda_runtime.h>

// CrossNetwork: x_l = x0 * (x_l . W_l) + b_l + x_l, L=6 layers.
// Identity: x_l = alpha_l * x0 + sum_{i<l} b_i, with
//   d_l = x0 . W_l ; C_l = (sum_{i<l} b_i) . W_l
//   s_l = alpha_l * d_l + C_l ; alpha_{l+1} = alpha_l + s_l ; alpha_0 = 1
//   out = alpha_L * x0 + sum_i b_i
// One read of x, one write of out: ~256 MB HBM traffic.
// R1: L1tex-bound -> reduce W refetch. R4: per-row barrier killed MLP.
// R5: __launch_bounds__(256,7) capped regs at 36 -> total spill -> timeout.
// R6: same tile design, NO min-blocks clamp, layer-outer accumulation to
//     keep regs ~90 (no spill, 2 blocks/SM).

#define D_DIM 2048
#define L_DIM 6
#define D_VEC (D_DIM / 4)      // 512 float4 per row
#define TPB   256
#define NWARP (TPB / 32)       // 8
#define ROWS  4                // rows per block (one tile, no loop)
#define PRE_BLKS 8

__device__ float g_Cpart[PRE_BLKS][L_DIM];  // per-block partial C_l
__device__ float g_bsum[D_DIM];             // sum_i b_i

// ---------------------------------------------------------------------------
// Kernel 1: 8 blocks x 256 threads; one column per thread.
// ---------------------------------------------------------------------------
__global__ __launch_bounds__(TPB) void precompute_kernel(
    const float* __restrict__ W, const float* __restrict__ b)
{
    const int t = threadIdx.x;
    const int d = blockIdx.x * TPB + t;     // 0..2047, exact cover

    float pc[L_DIM];
    float pre = 0.f;                         // prefix of b_i[d], i < l
#pragma unroll
    for (int l = 0; l < L_DIM; ++l) {
        pc[l] = pre * W[l * D_DIM + d];
        pre += b[l * D_DIM + d];
    }
    g_bsum[d] = pre;

#pragma unroll
    for (int l = 0; l < L_DIM; ++l) {
#pragma unroll
        for (int o = 16; o > 0; o >>= 1)
            pc[l] += __shfl_xor_sync(0xffffffffu, pc[l], o);
    }
    __shared__ float sred[NWARP][L_DIM];
    const int warp = t >> 5, lane = t & 31;
    if (lane == 0) {
#pragma unroll
        for (int l = 0; l < L_DIM; ++l) sred[warp][l] = pc[l];
    }
    __syncthreads();
    if (warp == 0) {
#pragma unroll
        for (int l = 0; l < L_DIM; ++l) {
            float v = (lane < NWARP) ? sred[lane][l] : 0.f;
#pragma unroll
            for (int o = 4; o > 0; o >>= 1)
                v += __shfl_xor_sync(0xffffffffu, v, o);
            if (lane == 0) g_Cpart[blockIdx.x][l] = v;
        }
    }
}

// ---------------------------------------------------------------------------
// Kernel 2: one block per 4-row tile. One barrier per tile, loads upfront.
// ---------------------------------------------------------------------------
__global__ __launch_bounds__(TPB) void cross_kernel(
    const float* __restrict__ x, const float* __restrict__ W,
    float* __restrict__ out)
{
    const int t = threadIdx.x;
    const int warp = t >> 5, lane = t & 31;

    const size_t base = (size_t)blockIdx.x * ROWS * D_VEC;
    const float4* x4 = reinterpret_cast<const float4*>(x) + base;

    // ---- Phase 0: all x loads upfront (8 independent LDG.128 -> MLP=8) ----
    float4 xa[ROWS], xb[ROWS];
#pragma unroll
    for (int r = 0; r < ROWS; ++r) {
        xa[r] = __ldcs(&x4[r * D_VEC + t]);
        xb[r] = __ldcs(&x4[r * D_VEC + t + TPB]);
    }

    // ---- Phase 1: layer-outer dot accumulation (W regs transient) ----------
    float p[ROWS][L_DIM];
#pragma unroll
    for (int l = 0; l < L_DIM; ++l) {
        const float4* w4 = reinterpret_cast<const float4*>(W) + l * D_VEC;
        const float4 wa = __ldg(&w4[t]);
        const float4 wb = __ldg(&w4[t + TPB]);
#pragma unroll
        for (int r = 0; r < ROWS; ++r) {
            p[r][l] = xa[r].x * wa.x + xa[r].y * wa.y
                    + xa[r].z * wa.z + xa[r].w * wa.w
                    + xb[r].x * wb.x + xb[r].y * wb.y
                    + xb[r].z * wb.z + xb[r].w * wb.w;
        }
    }

    // Warp-reduce all 24 partials, stage warp results to smem.
    __shared__ float sred[ROWS][NWARP][L_DIM];
#pragma unroll
    for (int r = 0; r < ROWS; ++r) {
#pragma unroll
        for (int l = 0; l < L_DIM; ++l) {
#pragma unroll
            for (int o = 16; o > 0; o >>= 1)
                p[r][l] += __shfl_xor_sync(0xffffffffu, p[r][l], o);
        }
        if (lane == 0) {
#pragma unroll
            for (int l = 0; l < L_DIM; ++l) sred[r][warp][l] = p[r][l];
        }
    }

    __syncthreads();   // the ONLY barrier: 1 per 4 rows

    // Row-invariant epilogue data (L1/L2-hit).
    const float4* bs4 = reinterpret_cast<const float4*>(g_bsum);
    const float4 ba = bs4[t];
    const float4 bb = bs4[t + TPB];
    float C[L_DIM];
#pragma unroll
    for (int l = 0; l < L_DIM; ++l) {
        float c = 0.f;
#pragma unroll
        for (int j = 0; j < PRE_BLKS; ++j) c += g_Cpart[j][l];
        C[l] = c;
    }

    // ---- Phase 2: per-row butterfly (every warp redundantly), alpha, store -
    // addr = wp*6 + l maps the 32 lanes of (v1,v2) loads to distinct banks.
    const int wp = lane & 7;
    const int lsel = lane >> 3;                   // 0..3
    float alpha[ROWS];
#pragma unroll
    for (int r = 0; r < ROWS; ++r) {
        float v1 = sred[r][wp][lsel];
        float v2 = (lane < 16) ? sred[r][wp][4 + lsel] : 0.f;
#pragma unroll
        for (int o = 1; o < 8; o <<= 1) {
            v1 += __shfl_xor_sync(0xffffffffu, v1, o);
            v2 += __shfl_xor_sync(0xffffffffu, v2, o);
        }
        float d[L_DIM];
        d[0] = __shfl_sync(0xffffffffu, v1, 0);
        d[1] = __shfl_sync(0xffffffffu, v1, 8);
        d[2] = __shfl_sync(0xffffffffu, v1, 16);
        d[3] = __shfl_sync(0xffffffffu, v1, 24);
        d[4] = __shfl_sync(0xffffffffu, v2, 0);
        d[5] = __shfl_sync(0xffffffffu, v2, 8);

        float a = 1.f;
#pragma unroll
        for (int l = 0; l < L_DIM; ++l)
            a += a * d[l] + C[l];
        alpha[r] = a;
    }

    float4* o4 = reinterpret_cast<float4*>(out) + base;
#pragma unroll
    for (int r = 0; r < ROWS; ++r) {
        const float a = alpha[r];
        float4 oa, ob;
        oa.x = a * xa[r].x + ba.x;  oa.y = a * xa[r].y + ba.y;
        oa.z = a * xa[r].z + ba.z;  oa.w = a * xa[r].w + ba.w;
        ob.x = a * xb[r].x + bb.x;  ob.y = a * xb[r].y + bb.y;
        ob.z = a * xb[r].z + bb.z;  ob.w = a * xb[r].w + bb.w;
        __stcs(&o4[r * D_VEC + t], oa);
        __stcs(&o4[r * D_VEC + t + TPB], ob);
    }
}

// ---------------------------------------------------------------------------
extern "C" void kernel_launch(void* const* d_in, const int* in_sizes, int n_in,
                              void* d_out, int out_size)
{
    const float* x = (const float*)d_in[0];   // [B, 2048]
    const float* W = (const float*)d_in[1];   // [6, 2048]
    const float* b = (const float*)d_in[2];   // [6, 2048]
    float* out = (float*)d_out;               // [B, 2048]

    const int B = in_sizes[0] / D_DIM;

    precompute_kernel<<<PRE_BLKS, TPB>>>(W, b);
    cross_kernel<<<B / ROWS, TPB>>>(x, W, out);
}

// round 9
// speedup vs baseline: 1.6358x; 1.2177x over previous
#include <cuda_runtime.h>

// CrossNetwork: x_l = x0 * (x_l . W_l) + b_l + x_l, L=6 layers.
// Identity: x_l = alpha_l * x0 + sum_{i<l} b_i, with
//   d_l = x0 . W_l ; C_l = (sum_{i<l} b_i) . W_l
//   s_l = alpha_l * d_l + C_l ; alpha_{l+1} = alpha_l + s_l ; alpha_0 = 1
//   out = alpha_L * x0 + sum_i b_i
// ~256 MB HBM traffic (one read of x, one write of out).
// R6 lesson: SHUFFLEs ride the l1tex pipe; 1440 shuffles/tile were 60% of the
// L1 load (72.5%). R7: batched pair-merge reduction -> 31 shuffles for all
// 24(+8 pad) sums per warp; cross-warp via warp0 + 2 cheap barriers; C_l
// pre-reduced to g_C[6] by a tiny 3rd kernel.

#define D_DIM 2048
#define L_DIM 6
#define D_VEC (D_DIM / 4)      // 512 float4 per row
#define TPB   256
#define NWARP (TPB / 32)       // 8
#define ROWS  4                // rows per block (one tile, no loop)
#define NVAL  (ROWS * L_DIM)   // 24 live reduction values
#define PRE_BLKS 8

__device__ float g_Cpart[PRE_BLKS][L_DIM];
__device__ float g_C[L_DIM];
__device__ float g_bsum[D_DIM];

// ---------------------------------------------------------------------------
// Kernel 1: 8 blocks x 256 threads; one column per thread.
// ---------------------------------------------------------------------------
__global__ __launch_bounds__(TPB) void precompute_kernel(
    const float* __restrict__ W, const float* __restrict__ b)
{
    const int t = threadIdx.x;
    const int d = blockIdx.x * TPB + t;     // 0..2047, exact cover

    float pc[L_DIM];
    float pre = 0.f;                         // prefix of b_i[d], i < l
#pragma unroll
    for (int l = 0; l < L_DIM; ++l) {
        pc[l] = pre * W[l * D_DIM + d];
        pre += b[l * D_DIM + d];
    }
    g_bsum[d] = pre;

#pragma unroll
    for (int l = 0; l < L_DIM; ++l) {
#pragma unroll
        for (int o = 16; o > 0; o >>= 1)
            pc[l] += __shfl_xor_sync(0xffffffffu, pc[l], o);
    }
    __shared__ float sred[NWARP][L_DIM];
    const int warp = t >> 5, lane = t & 31;
    if (lane == 0) {
#pragma unroll
        for (int l = 0; l < L_DIM; ++l) sred[warp][l] = pc[l];
    }
    __syncthreads();
    if (warp == 0) {
#pragma unroll
        for (int l = 0; l < L_DIM; ++l) {
            float v = (lane < NWARP) ? sred[lane][l] : 0.f;
#pragma unroll
            for (int o = 4; o > 0; o >>= 1)
                v += __shfl_xor_sync(0xffffffffu, v, o);
            if (lane == 0) g_Cpart[blockIdx.x][l] = v;
        }
    }
}

// ---------------------------------------------------------------------------
// Kernel 1b: fold g_Cpart -> g_C[6]. One warp, negligible.
// ---------------------------------------------------------------------------
__global__ void reduceC_kernel()
{
    const int l = threadIdx.x;
    if (l < L_DIM) {
        float c = 0.f;
#pragma unroll
        for (int j = 0; j < PRE_BLKS; ++j) c += g_Cpart[j][l];
        g_C[l] = c;
    }
}

// ---------------------------------------------------------------------------
// Kernel 2: one block per 4-row tile.
// ---------------------------------------------------------------------------
__global__ __launch_bounds__(TPB) void cross_kernel(
    const float* __restrict__ x, const float* __restrict__ W,
    float* __restrict__ out)
{
    const int t = threadIdx.x;
    const int warp = t >> 5, lane = t & 31;

    const size_t base = (size_t)blockIdx.x * ROWS * D_VEC;
    const float4* x4 = reinterpret_cast<const float4*>(x) + base;

    // ---- Phase 0: all x loads upfront (8 independent LDG.128, MLP=8) ------
    float4 xa[ROWS], xb[ROWS];
#pragma unroll
    for (int r = 0; r < ROWS; ++r) {
        xa[r] = __ldcs(&x4[r * D_VEC + t]);
        xb[r] = __ldcs(&x4[r * D_VEC + t + TPB]);
    }

    // Row-invariant scalars (L2 hits, uniform -> 1 wavefront each).
    float C[L_DIM];
#pragma unroll
    for (int l = 0; l < L_DIM; ++l) C[l] = g_C[l];

    // ---- Phase 1: layer-outer dot accumulation into v[0..23], pad to 32 ---
    float v[32];
#pragma unroll
    for (int i = NVAL; i < 32; ++i) v[i] = 0.f;
#pragma unroll
    for (int l = 0; l < L_DIM; ++l) {
        const float4* w4 = reinterpret_cast<const float4*>(W) + l * D_VEC;
        const float4 wa = __ldg(&w4[t]);
        const float4 wb = __ldg(&w4[t + TPB]);
#pragma unroll
        for (int r = 0; r < ROWS; ++r) {
            v[r * L_DIM + l] =
                  xa[r].x * wa.x + xa[r].y * wa.y
                + xa[r].z * wa.z + xa[r].w * wa.w
                + xb[r].x * wb.x + xb[r].y * wb.y
                + xb[r].z * wb.z + xb[r].w * wb.w;
        }
    }

    // bsum for the epilogue (L1/L2 hits).
    const float4* bs4 = reinterpret_cast<const float4*>(g_bsum);
    const float4 ba = bs4[t];
    const float4 bb = bs4[t + TPB];

    // ---- Batched pair-merge warp reduction: 31 shuffles for 32 sums. ------
    // After level d, lanes with bit d hold the upper-half values; final:
    // lane L holds the complete warp-sum of value L in v[0].
#pragma unroll
    for (int d = 16; d >= 1; d >>= 1) {
#pragma unroll
        for (int i = 0; i < d; ++i) {
            const float send = (lane & d) ? v[i] : v[i + d];
            const float got = __shfl_xor_sync(0xffffffffu, send, d);
            v[i] = ((lane & d) ? v[i + d] : v[i]) + got;
        }
    }

    __shared__ float sred[NWARP][32];
    __shared__ __align__(16) float sd[32];
    if (lane < NVAL) sred[warp][lane] = v[0];
    __syncthreads();

    // ---- Cross-warp: warp0 sums 8 partials per value (conflict-free). -----
    if (warp == 0 && lane < NVAL) {
        float acc = 0.f;
#pragma unroll
        for (int w = 0; w < NWARP; ++w) acc += sred[w][lane];
        sd[lane] = acc;
    }
    __syncthreads();

    // ---- Phase 2: broadcast 24 dots via 6 LDS.128, alphas, store. ---------
    const float4* sd4 = reinterpret_cast<const float4*>(sd);
    float ds[NVAL];
#pragma unroll
    for (int q = 0; q < NVAL / 4; ++q) {
        const float4 dv = sd4[q];
        ds[q * 4 + 0] = dv.x;  ds[q * 4 + 1] = dv.y;
        ds[q * 4 + 2] = dv.z;  ds[q * 4 + 3] = dv.w;
    }

    float4* o4 = reinterpret_cast<float4*>(out) + base;
#pragma unroll
    for (int r = 0; r < ROWS; ++r) {
        float a = 1.f;
#pragma unroll
        for (int l = 0; l < L_DIM; ++l)
            a += a * ds[r * L_DIM + l] + C[l];

        float4 oa, ob;
        oa.x = a * xa[r].x + ba.x;  oa.y = a * xa[r].y + ba.y;
        oa.z = a * xa[r].z + ba.z;  oa.w = a * xa[r].w + ba.w;
        ob.x = a * xb[r].x + bb.x;  ob.y = a * xb[r].y + bb.y;
        ob.z = a * xb[r].z + bb.z;  ob.w = a * xb[r].w + bb.w;
        __stcs(&o4[r * D_VEC + t], oa);
        __stcs(&o4[r * D_VEC + t + TPB], ob);
    }
}

// ---------------------------------------------------------------------------
extern "C" void kernel_launch(void* const* d_in, const int* in_sizes, int n_in,
                              void* d_out, int out_size)
{
    const float* x = (const float*)d_in[0];   // [B, 2048]
    const float* W = (const float*)d_in[1];   // [6, 2048]
    const float* b = (const float*)d_in[2];   // [6, 2048]
    float* out = (float*)d_out;               // [B, 2048]

    const int B = in_sizes[0] / D_DIM;

    precompute_kernel<<<PRE_BLKS, TPB>>>(W, b);
    reduceC_kernel<<<1, 32>>>();
    cross_kernel<<<B / ROWS, TPB>>>(x, W, out);
}